// round 3
// baseline (speedup 1.0000x reference)
#include <cuda_runtime.h>
#include <cuda_bf16.h>
#include <cstdint>

#define F 128
#define RCUT 5.0f
#define TN 16
#define NPAIR 8
#define NODE_BLOCK 128
#define NODE_GRID 444
#define MAX_NODES 100000

// Scratch (allocation-free rule: __device__ globals)
__device__ float  q_dev[MAX_NODES];
__device__ float4 mu4_dev[MAX_NODES];

// ---------- f32x2 packed helpers (sm_100+) ----------
static __device__ __forceinline__ unsigned long long pack2(float lo, float hi) {
    unsigned long long r;
    asm("mov.b64 %0, {%1, %2};" : "=l"(r) : "f"(lo), "f"(hi));
    return r;
}
static __device__ __forceinline__ void unpack2(unsigned long long v, float& lo, float& hi) {
    asm("mov.b64 {%0, %1}, %2;" : "=f"(lo), "=f"(hi) : "l"(v));
}
static __device__ __forceinline__ unsigned long long fma2(unsigned long long a,
                                                          unsigned long long b,
                                                          unsigned long long c) {
    unsigned long long d;
    asm("fma.rn.f32x2 %0, %1, %2, %3;" : "=l"(d) : "l"(a), "l"(b), "l"(c));
    return d;
}
static __device__ __forceinline__ unsigned long long add2(unsigned long long a,
                                                          unsigned long long b) {
    unsigned long long d;
    asm("add.rn.f32x2 %0, %1, %2;" : "=l"(d) : "l"(a), "l"(b));
    return d;
}
static __device__ __forceinline__ float silu_f(float z) {
    return __fdividef(z, 1.0f + __expf(-z));
}

// ---------- Kernel 1: zero the float4 accumulation scratch ----------
__global__ void zero_kernel(int n_nodes) {
    int i = blockIdx.x * blockDim.x + threadIdx.x;
    if (i < n_nodes) mu4_dev[i] = make_float4(0.f, 0.f, 0.f, 0.f);
}

// ---------- Kernel 2: node MLP -> q ----------
// Block = 128 threads (thread = output feature f). Tile = 16 nodes (8 f32x2 pairs).
// W1 staged once per block in smem as [k][f] (conflict-free across lanes).
// x tile staged as node-pair-interleaved float4: (x[n0,k], x[n1,k], x[n0,k+1], x[n1,k+1])
// so the inner loop runs on packed fma.rn.f32x2 (2x scalar FFMA throughput).
__global__ void __launch_bounds__(NODE_BLOCK, 3)
node_q_kernel(const float* __restrict__ x, const float* __restrict__ W1,
              const float* __restrict__ b1, const float* __restrict__ W2,
              const float* __restrict__ b2, int n_nodes) {
    extern __shared__ float smem[];
    float* W1s = smem;                                          // 16384 floats (64 KB)
    float4* xs4 = (float4*)(smem + F * F);                      // 512 float4 (8 KB)
    float2* red = (float2*)(smem + F * F + NPAIR * (F / 2) * 4);// 32 float2

    const int tid  = threadIdx.x;
    const int f    = tid;
    const int warp = tid >> 5;
    const int lane = tid & 31;

    // Stage W1 (row-major [k][f], exactly the global layout)
    {
        const float4* g = (const float4*)W1;
        float4* s = (float4*)W1s;
        #pragma unroll
        for (int i = tid; i < (F * F) / 4; i += NODE_BLOCK) s[i] = g[i];
    }
    const float b1f = b1[f];
    const float w2f = W2[f];
    const float b2v = b2[0];
    const unsigned long long b1p = pack2(b1f, b1f);
    __syncthreads();

    const int n_tiles = n_nodes / TN;  // 100000 / 16 = 6250, exact
    for (int tile = blockIdx.x; tile < n_tiles; tile += gridDim.x) {
        const int base = tile * TN;

        // Load x tile into interleaved pair layout
        for (int i = tid; i < NPAIR * (F / 2); i += NODE_BLOCK) {
            int p  = i >> 6;      // pair index
            int k2 = i & 63;      // k/2
            const float2 a = *(const float2*)(x + (size_t)(base + 2 * p)     * F + 2 * k2);
            const float2 b = *(const float2*)(x + (size_t)(base + 2 * p + 1) * F + 2 * k2);
            xs4[i] = make_float4(a.x, b.x, a.y, b.y);
        }
        __syncthreads();

        unsigned long long acc[NPAIR];
        #pragma unroll
        for (int p = 0; p < NPAIR; p++) acc[p] = b1p;

        const ulonglong2* xsu = (const ulonglong2*)xs4;
        #pragma unroll 2
        for (int k2 = 0; k2 < F / 2; k2++) {
            const float w0 = W1s[(2 * k2)     * F + f];
            const float w1 = W1s[(2 * k2 + 1) * F + f];
            const unsigned long long w0p = pack2(w0, w0);
            const unsigned long long w1p = pack2(w1, w1);
            #pragma unroll
            for (int p = 0; p < NPAIR; p++) {
                const ulonglong2 xv = xsu[p * (F / 2) + k2];  // broadcast LDS.128
                acc[p] = fma2(xv.x, w0p, acc[p]);
                acc[p] = fma2(xv.y, w1p, acc[p]);
            }
        }

        // silu(h) * W2[f], packed
        unsigned long long cp[NPAIR];
        #pragma unroll
        for (int p = 0; p < NPAIR; p++) {
            float h0, h1;
            unpack2(acc[p], h0, h1);
            cp[p] = pack2(silu_f(h0) * w2f, silu_f(h1) * w2f);
        }

        // Butterfly reduce over the 32 lanes (features within warp)
        #pragma unroll
        for (int off = 16; off > 0; off >>= 1) {
            #pragma unroll
            for (int p = 0; p < NPAIR; p++) {
                unsigned long long o = __shfl_xor_sync(0xffffffffu, cp[p], off);
                cp[p] = add2(cp[p], o);
            }
        }
        if (lane == 0) {
            #pragma unroll
            for (int p = 0; p < NPAIR; p++) {
                float a, b;
                unpack2(cp[p], a, b);
                red[warp * NPAIR + p] = make_float2(a, b);
            }
        }
        __syncthreads();
        if (tid < NPAIR) {
            const float2 s0 = red[tid];
            const float2 s1 = red[NPAIR + tid];
            const float2 s2 = red[2 * NPAIR + tid];
            const float2 s3 = red[3 * NPAIR + tid];
            const float sx = (s0.x + s1.x) + (s2.x + s3.x);
            const float sy = (s0.y + s1.y) + (s2.y + s3.y);
            q_dev[base + 2 * tid]     = silu_f(sx + b2v);
            q_dev[base + 2 * tid + 1] = silu_f(sy + b2v);
        }
        __syncthreads();  // protect xs4/red before next tile
    }
}

// ---------- Kernel 3: edge pass with single float4 RED per edge ----------
__global__ void __launch_bounds__(256)
edge_kernel(const float* __restrict__ rij, const float* __restrict__ vij,
            const int* __restrict__ src, const int* __restrict__ dst, int n_edges) {
    const int e = blockIdx.x * blockDim.x + threadIdx.x;
    if (e >= n_edges) return;
    const float r = __ldg(rij + e);
    const int   s = __ldg(src + e);
    const int   d = __ldg(dst + e);
    float c = 0.5f * (__cosf(r * (3.14159265358979323846f / RCUT)) + 1.0f);
    if (r >= RCUT) c = 0.0f;
    const float scale = __ldg(&q_dev[s]) * c;
    const size_t ev = (size_t)e * 3;
    const float v0 = __ldg(vij + ev);
    const float v1 = __ldg(vij + ev + 1);
    const float v2 = __ldg(vij + ev + 2);
    atomicAdd(&mu4_dev[d], make_float4(v0 * scale, v1 * scale, v2 * scale, 0.0f));
}

// ---------- Kernel 4: compact [N,4] scratch -> [N,3] output ----------
__global__ void copy_kernel(float* __restrict__ out, int n_nodes) {
    const int n = blockIdx.x * blockDim.x + threadIdx.x;
    if (n < n_nodes) {
        const float4 v = mu4_dev[n];
        out[3 * n]     = v.x;
        out[3 * n + 1] = v.y;
        out[3 * n + 2] = v.z;
    }
}

extern "C" void kernel_launch(void* const* d_in, const int* in_sizes, int n_in,
                              void* d_out, int out_size) {
    const float* x   = (const float*)d_in[0];
    const float* rij = (const float*)d_in[1];
    const float* vij = (const float*)d_in[2];
    const int*   src = (const int*)d_in[3];
    const int*   dst = (const int*)d_in[4];
    const float* W1  = (const float*)d_in[5];
    const float* b1  = (const float*)d_in[6];
    const float* W2  = (const float*)d_in[7];
    const float* b2  = (const float*)d_in[8];
    float* out = (float*)d_out;

    const int n_nodes = in_sizes[0] / F;   // 100000
    const int n_edges = in_sizes[1];       // 6400000

    const int smem_bytes = F * F * 4 + NPAIR * (F / 2) * 16 + 4 * NPAIR * 8; // 73984
    cudaFuncSetAttribute(node_q_kernel,
                         cudaFuncAttributeMaxDynamicSharedMemorySize, smem_bytes);

    zero_kernel<<<(n_nodes + 255) / 256, 256>>>(n_nodes);
    node_q_kernel<<<NODE_GRID, NODE_BLOCK, smem_bytes>>>(x, W1, b1, W2, b2, n_nodes);
    edge_kernel<<<(n_edges + 255) / 256, 256>>>(rij, vij, src, dst, n_edges);
    copy_kernel<<<(n_nodes + 255) / 256, 256>>>(out, n_nodes);
}

// round 5
// speedup vs baseline: 1.0217x; 1.0217x over previous
#include <cuda_runtime.h>
#include <cuda_bf16.h>
#include <cstdint>

#define F 128
#define RCUT 5.0f
#define TN 16
#define NPAIR 8
#define NODE_BLOCK 128
#define NODE_GRID 444
#define MAX_NODES 100000

// Scratch (allocation-free rule: __device__ globals)
__device__ float  q_dev[MAX_NODES];
__device__ float4 mu4_dev[MAX_NODES];

// ---------- f32x2 packed helpers (sm_100+) ----------
static __device__ __forceinline__ unsigned long long pack2(float lo, float hi) {
    unsigned long long r;
    asm("mov.b64 %0, {%1, %2};" : "=l"(r) : "f"(lo), "f"(hi));
    return r;
}
static __device__ __forceinline__ void unpack2(unsigned long long v, float& lo, float& hi) {
    asm("mov.b64 {%0, %1}, %2;" : "=f"(lo), "=f"(hi) : "l"(v));
}
static __device__ __forceinline__ unsigned long long fma2(unsigned long long a,
                                                          unsigned long long b,
                                                          unsigned long long c) {
    unsigned long long d;
    asm("fma.rn.f32x2 %0, %1, %2, %3;" : "=l"(d) : "l"(a), "l"(b), "l"(c));
    return d;
}
static __device__ __forceinline__ unsigned long long add2(unsigned long long a,
                                                          unsigned long long b) {
    unsigned long long d;
    asm("add.rn.f32x2 %0, %1, %2;" : "=l"(d) : "l"(a), "l"(b));
    return d;
}
static __device__ __forceinline__ float silu_f(float z) {
    return __fdividef(z, 1.0f + __expf(-z));
}

// ---------- Kernel 1: node MLP -> q (also zeroes mu4 scratch) ----------
// Block = 128 threads (thread = output feature f). Tile = 16 nodes (8 f32x2 pairs).
// W1 staged once per block in smem as [k][f] (conflict-free across lanes).
// x tile staged as node-pair-interleaved float4 so the inner loop runs on
// packed fma.rn.f32x2 (2x scalar FFMA throughput).
__global__ void __launch_bounds__(NODE_BLOCK, 3)
node_q_kernel(const float* __restrict__ x, const float* __restrict__ W1,
              const float* __restrict__ b1, const float* __restrict__ W2,
              const float* __restrict__ b2, int n_nodes) {
    extern __shared__ float smem[];
    float* W1s = smem;                                          // 16384 floats (64 KB)
    float4* xs4 = (float4*)(smem + F * F);                      // 512 float4 (8 KB)
    float2* red = (float2*)(smem + F * F + NPAIR * (F / 2) * 4);// 32 float2

    const int tid  = threadIdx.x;
    const int f    = tid;
    const int warp = tid >> 5;
    const int lane = tid & 31;

    // Zero the accumulation scratch (edge kernel runs after us -> ordered)
    for (int i = blockIdx.x * NODE_BLOCK + tid; i < n_nodes; i += gridDim.x * NODE_BLOCK)
        mu4_dev[i] = make_float4(0.f, 0.f, 0.f, 0.f);

    // Stage W1 (row-major [k][f], exactly the global layout)
    {
        const float4* g = (const float4*)W1;
        float4* s = (float4*)W1s;
        #pragma unroll
        for (int i = tid; i < (F * F) / 4; i += NODE_BLOCK) s[i] = g[i];
    }
    const float b1f = b1[f];
    const float w2f = W2[f];
    const float b2v = b2[0];
    const unsigned long long b1p = pack2(b1f, b1f);
    __syncthreads();

    const int n_tiles = n_nodes / TN;  // 100000 / 16 = 6250, exact
    for (int tile = blockIdx.x; tile < n_tiles; tile += gridDim.x) {
        const int base = tile * TN;

        // Load x tile into interleaved pair layout
        for (int i = tid; i < NPAIR * (F / 2); i += NODE_BLOCK) {
            int p  = i >> 6;      // pair index
            int k2 = i & 63;      // k/2
            const float2 a = *(const float2*)(x + (size_t)(base + 2 * p)     * F + 2 * k2);
            const float2 b = *(const float2*)(x + (size_t)(base + 2 * p + 1) * F + 2 * k2);
            xs4[i] = make_float4(a.x, b.x, a.y, b.y);
        }
        __syncthreads();

        unsigned long long acc[NPAIR];
        #pragma unroll
        for (int p = 0; p < NPAIR; p++) acc[p] = b1p;

        const ulonglong2* xsu = (const ulonglong2*)xs4;
        #pragma unroll 2
        for (int k2 = 0; k2 < F / 2; k2++) {
            const float w0 = W1s[(2 * k2)     * F + f];
            const float w1 = W1s[(2 * k2 + 1) * F + f];
            const unsigned long long w0p = pack2(w0, w0);
            const unsigned long long w1p = pack2(w1, w1);
            #pragma unroll
            for (int p = 0; p < NPAIR; p++) {
                const ulonglong2 xv = xsu[p * (F / 2) + k2];  // broadcast LDS.128
                acc[p] = fma2(xv.x, w0p, acc[p]);
                acc[p] = fma2(xv.y, w1p, acc[p]);
            }
        }

        // silu(h) * W2[f], packed
        unsigned long long cp[NPAIR];
        #pragma unroll
        for (int p = 0; p < NPAIR; p++) {
            float h0, h1;
            unpack2(acc[p], h0, h1);
            cp[p] = pack2(silu_f(h0) * w2f, silu_f(h1) * w2f);
        }

        // Butterfly reduce over the 32 lanes (features within warp)
        #pragma unroll
        for (int off = 16; off > 0; off >>= 1) {
            #pragma unroll
            for (int p = 0; p < NPAIR; p++) {
                unsigned long long o = __shfl_xor_sync(0xffffffffu, cp[p], off);
                cp[p] = add2(cp[p], o);
            }
        }
        if (lane == 0) {
            #pragma unroll
            for (int p = 0; p < NPAIR; p++) {
                float a, b;
                unpack2(cp[p], a, b);
                red[warp * NPAIR + p] = make_float2(a, b);
            }
        }
        __syncthreads();
        if (tid < NPAIR) {
            const float2 s0 = red[tid];
            const float2 s1 = red[NPAIR + tid];
            const float2 s2 = red[2 * NPAIR + tid];
            const float2 s3 = red[3 * NPAIR + tid];
            const float sx = (s0.x + s1.x) + (s2.x + s3.x);
            const float sy = (s0.y + s1.y) + (s2.y + s3.y);
            q_dev[base + 2 * tid]     = silu_f(sx + b2v);
            q_dev[base + 2 * tid + 1] = silu_f(sy + b2v);
        }
        __syncthreads();  // protect xs4/red before next tile
    }
}

// ---------- Kernel 2: edge pass, 4 edges/thread, vectorized LSU traffic ----
// Per 4 edges: 1 LDG.128 rij + 1 LDG.128 src + 1 LDG.128 dst + 3 LDG.128 vij
//            + 4 scalar q gathers + 4 RED.128   (14 LSU ops vs 28 scalar)
__global__ void __launch_bounds__(256)
edge_kernel4(const float4* __restrict__ rij4, const float4* __restrict__ vij4,
             const int4* __restrict__ src4, const int4* __restrict__ dst4,
             int n_quads) {
    const int i = blockIdx.x * blockDim.x + threadIdx.x;
    if (i >= n_quads) return;

    const float4 r = rij4[i];
    const int4   s = src4[i];
    const int4   d = dst4[i];
    const float4 a = vij4[(size_t)3 * i];
    const float4 b = vij4[(size_t)3 * i + 1];
    const float4 c = vij4[(size_t)3 * i + 2];

    const float k = 3.14159265358979323846f / RCUT;
    float c0 = 0.5f * (__cosf(r.x * k) + 1.0f); if (r.x >= RCUT) c0 = 0.0f;
    float c1 = 0.5f * (__cosf(r.y * k) + 1.0f); if (r.y >= RCUT) c1 = 0.0f;
    float c2 = 0.5f * (__cosf(r.z * k) + 1.0f); if (r.z >= RCUT) c2 = 0.0f;
    float c3 = 0.5f * (__cosf(r.w * k) + 1.0f); if (r.w >= RCUT) c3 = 0.0f;

    const float s0 = __ldg(&q_dev[s.x]) * c0;
    const float s1 = __ldg(&q_dev[s.y]) * c1;
    const float s2 = __ldg(&q_dev[s.z]) * c2;
    const float s3 = __ldg(&q_dev[s.w]) * c3;

    atomicAdd(&mu4_dev[d.x], make_float4(a.x * s0, a.y * s0, a.z * s0, 0.0f));
    atomicAdd(&mu4_dev[d.y], make_float4(a.w * s1, b.x * s1, b.y * s1, 0.0f));
    atomicAdd(&mu4_dev[d.z], make_float4(b.z * s2, b.w * s2, c.x * s2, 0.0f));
    atomicAdd(&mu4_dev[d.w], make_float4(c.y * s3, c.z * s3, c.w * s3, 0.0f));
}

// ---------- Kernel 3: compact [N,4] scratch -> [N,3] output, 4 nodes/thread --
__global__ void copy_kernel4(float4* __restrict__ out4, int n_quads) {
    const int i = blockIdx.x * blockDim.x + threadIdx.x;
    if (i >= n_quads) return;
    const float4 m0 = mu4_dev[4 * i];
    const float4 m1 = mu4_dev[4 * i + 1];
    const float4 m2 = mu4_dev[4 * i + 2];
    const float4 m3 = mu4_dev[4 * i + 3];
    out4[3 * i]     = make_float4(m0.x, m0.y, m0.z, m1.x);
    out4[3 * i + 1] = make_float4(m1.y, m1.z, m2.x, m2.y);
    out4[3 * i + 2] = make_float4(m2.z, m3.x, m3.y, m3.z);
}

extern "C" void kernel_launch(void* const* d_in, const int* in_sizes, int n_in,
                              void* d_out, int out_size) {
    const float* x   = (const float*)d_in[0];
    const float* rij = (const float*)d_in[1];
    const float* vij = (const float*)d_in[2];
    const int*   src = (const int*)d_in[3];
    const int*   dst = (const int*)d_in[4];
    const float* W1  = (const float*)d_in[5];
    const float* b1  = (const float*)d_in[6];
    const float* W2  = (const float*)d_in[7];
    const float* b2  = (const float*)d_in[8];
    float* out = (float*)d_out;

    const int n_nodes = in_sizes[0] / F;   // 100000
    const int n_edges = in_sizes[1];       // 6400000

    const int smem_bytes = F * F * 4 + NPAIR * (F / 2) * 16 + 4 * NPAIR * 8; // 73984
    cudaFuncSetAttribute(node_q_kernel,
                         cudaFuncAttributeMaxDynamicSharedMemorySize, smem_bytes);

    node_q_kernel<<<NODE_GRID, NODE_BLOCK, smem_bytes>>>(x, W1, b1, W2, b2, n_nodes);

    const int eq = n_edges / 4;            // 1,600,000 (exact)
    edge_kernel4<<<(eq + 255) / 256, 256>>>((const float4*)rij, (const float4*)vij,
                                            (const int4*)src, (const int4*)dst, eq);

    const int nq = n_nodes / 4;            // 25,000 (exact)
    copy_kernel4<<<(nq + 255) / 256, 256>>>((float4*)out, nq);
}